// round 15
// baseline (speedup 1.0000x reference)
#include <cuda_runtime.h>
#include <cstdint>
#include <math.h>

#define N_TOK 8192
#define C_DIM 768
#define H_DIM 3072
#define N_EXP 8

#define BM 192
#define BN 192
#define BKF 32                    // K floats per chunk
#define STAGES 3
#define SROW 36                   // padded smem row stride (floats)
#define A_STAGE_F (BM * SROW)     // 6912 floats
#define B_STAGE_F (BN * SROW)     // 6912 floats
#define STAGE_F   (A_STAGE_F + B_STAGE_F)   // 13824 floats
#define SMEM_TOTAL (STAGES * STAGE_F * 4)   // 165888 bytes
#define THREADS 384

#define KT1 (C_DIM / BKF)         // 24
#define KT2 (H_DIM / BKF)         // 96
#define MTILES ((N_TOK + BM - 1) / BM)   // 43

// ---- static device scratch ----
__device__ int   g_cnt[N_EXP];
__device__ int   g_base[N_EXP];
__device__ int   g_tok[N_EXP * N_TOK];
__device__ float g_gate[N_EXP * N_TOK];
__device__ int   g_epos[2 * N_TOK];
__device__ float g_h[(size_t)2 * N_TOK * H_DIM];          // tf32-rounded hidden
__device__ float g_y[(size_t)2 * N_TOK * C_DIM];
__device__ float g_xr[(size_t)N_TOK * C_DIM];             // tf32-rounded x
__device__ float g_wfc[(size_t)N_EXP * H_DIM * C_DIM];    // tf32-rounded w_fc
__device__ float g_wp[(size_t)N_EXP * C_DIM * H_DIM];     // tf32-rounded w_proj

// =============== helpers ===============
__device__ __forceinline__ uint32_t smem_u32(const void* p) {
    uint32_t a;
    asm("{ .reg .u64 t; cvta.to.shared.u64 t, %1; cvt.u32.u64 %0, t; }" : "=r"(a) : "l"(p));
    return a;
}
__device__ __forceinline__ void cp16(uint32_t dst, const void* src) {
    asm volatile("cp.async.cg.shared.global [%0], [%1], 16;" :: "r"(dst), "l"(src) : "memory");
}
__device__ __forceinline__ void cp_commit() { asm volatile("cp.async.commit_group;" ::: "memory"); }
template <int N> __device__ __forceinline__ void cp_wait() {
    asm volatile("cp.async.wait_group %0;" :: "n"(N) : "memory");
}
__device__ __forceinline__ float tf32r(float x) {
    uint32_t r;
    asm("cvt.rna.tf32.f32 %0, %1;" : "=r"(r) : "f"(x));
    return __uint_as_float(r);
}
__device__ __forceinline__ void mma8(float* c, const uint32_t* a, const uint32_t* b) {
    asm volatile(
        "mma.sync.aligned.m16n8k8.row.col.f32.tf32.tf32.f32 "
        "{%0,%1,%2,%3},{%4,%5,%6,%7},{%8,%9},{%0,%1,%2,%3};"
        : "+f"(c[0]), "+f"(c[1]), "+f"(c[2]), "+f"(c[3])
        : "r"(a[0]), "r"(a[1]), "r"(a[2]), "r"(a[3]), "r"(b[0]), "r"(b[1]));
}
__device__ __forceinline__ float gelu_tanh(float v) {
    float t = 0.7978845608028654f * (v + 0.044715f * v * v * v);
    return 0.5f * v * (1.0f + tanhf(t));
}

// =============== small kernels ===============
__global__ void zero_kernel() {
    if (threadIdx.x < N_EXP) g_cnt[threadIdx.x] = 0;
}

__global__ void round_kernel(const float4* __restrict__ src, float4* __restrict__ dst, int n4) {
    int i = blockIdx.x * blockDim.x + threadIdx.x;
    if (i < n4) {
        float4 v = src[i];
        v.x = tf32r(v.x); v.y = tf32r(v.y); v.z = tf32r(v.z); v.w = tf32r(v.w);
        dst[i] = v;
    }
}

__global__ void gate_kernel(const float* __restrict__ x,
                            const float* __restrict__ gw,
                            const float* __restrict__ gb) {
    __shared__ float sw[N_EXP * C_DIM];
    for (int i = threadIdx.x; i < N_EXP * C_DIM; i += blockDim.x) sw[i] = gw[i];
    __syncthreads();

    int warp = threadIdx.x >> 5, lane = threadIdx.x & 31;
    int tok = blockIdx.x * 8 + warp;
    const float* xr = x + (size_t)tok * C_DIM;

    float acc[8] = {0, 0, 0, 0, 0, 0, 0, 0};
    for (int c = lane; c < C_DIM; c += 32) {
        float xv = xr[c];
#pragma unroll
        for (int e = 0; e < 8; e++) acc[e] += xv * sw[e * C_DIM + c];
    }
#pragma unroll
    for (int off = 16; off; off >>= 1)
#pragma unroll
        for (int e = 0; e < 8; e++)
            acc[e] += __shfl_down_sync(0xffffffffu, acc[e], off);

    if (lane == 0) {
        float s[8];
#pragma unroll
        for (int e = 0; e < 8; e++) s[e] = acc[e] + gb[e];
        float s0 = s[0]; int e0 = 0;
#pragma unroll
        for (int e = 1; e < 8; e++) if (s[e] > s0) { s0 = s[e]; e0 = e; }
        float s1 = -1e30f; int e1 = 0;
#pragma unroll
        for (int e = 0; e < 8; e++) {
            if (e == e0) continue;
            if (s[e] > s1) { s1 = s[e]; e1 = e; }
        }
        float g0 = 1.0f / (1.0f + expf(s1 - s0));
        float g1 = 1.0f - g0;

        int p0 = atomicAdd(&g_cnt[e0], 1);
        g_tok[e0 * N_TOK + p0] = tok;
        g_gate[e0 * N_TOK + p0] = g0;
        int p1 = atomicAdd(&g_cnt[e1], 1);
        g_tok[e1 * N_TOK + p1] = tok;
        g_gate[e1 * N_TOK + p1] = g1;
        g_epos[2 * tok + 0] = (e0 << 16) | p0;
        g_epos[2 * tok + 1] = (e1 << 16) | p1;
    }
}

__global__ void prefix_kernel() {
    if (threadIdx.x == 0) {
        int b = 0;
        for (int e = 0; e < N_EXP; e++) { g_base[e] = b; b += g_cnt[e]; }
    }
}

// =============== shared mma.sync mainloop ===============
// CTA tile 192x192, 12 warps in 3x4 grid, warp tile 64x48. 384 threads.
// A and B loaders symmetric: 192 rows, 2 threads/row, 4x cp16 each.
__device__ __forceinline__ void gemm_mainloop(float* smf, uint32_t sb,
                                              const float* aRow, const float* bRow,
                                              int KT, float acc[4][6][4]) {
    int tid = threadIdx.x;
    int wid = tid >> 5, lane = tid & 31;
    int wm = wid >> 2, wn = wid & 3;      // 3x4 warp grid, 64x48 warp tile
    int lq = lane >> 2, lr = lane & 3;

    uint32_t abase = sb + (uint32_t)((tid >> 1) * SROW * 4 + (tid & 1) * 64);
    uint32_t bbase = sb + (uint32_t)(A_STAGE_F * 4 + (tid >> 1) * SROW * 4 + (tid & 1) * 64);

#pragma unroll
    for (int c = 0; c < STAGES - 1; ++c) {
        uint32_t so = (uint32_t)(c * STAGE_F * 4);
        const float* as = aRow + c * BKF;
        const float* bs = bRow + c * BKF;
#pragma unroll
        for (int q = 0; q < 4; q++) cp16(abase + so + q * 16, as + q * 4);
#pragma unroll
        for (int q = 0; q < 4; q++) cp16(bbase + so + q * 16, bs + q * 4);
        cp_commit();
    }

    const float* aFrag = smf + (wm * 64 + lq) * SROW + lr;
    const float* bFrag = smf + A_STAGE_F + (wn * 48 + lq) * SROW + lr;

    int st = 0;                    // compute stage
    int lst = STAGES - 1;          // load stage

#pragma unroll 1
    for (int kt = 0; kt < KT; ++kt) {
        cp_wait<STAGES - 2>();
        __syncthreads();

        int lc = kt + STAGES - 1;
        if (lc < KT) {
            uint32_t so = (uint32_t)(lst * STAGE_F * 4);
            const float* as = aRow + lc * BKF;
            const float* bs = bRow + lc * BKF;
#pragma unroll
            for (int q = 0; q < 4; q++) cp16(abase + so + q * 16, as + q * 4);
#pragma unroll
            for (int q = 0; q < 4; q++) cp16(bbase + so + q * 16, bs + q * 4);
        }
        cp_commit();   // always commit (keeps wait_group accounting uniform)

        const float* aS = aFrag + st * STAGE_F;
        const float* bS = bFrag + st * STAGE_F;

#pragma unroll
        for (int kk = 0; kk < 4; kk++) {
            uint32_t af[4][4], bf[6][2];
#pragma unroll
            for (int mt = 0; mt < 4; mt++) {
                const float* p = aS + mt * 16 * SROW + kk * 8;
                af[mt][0] = __float_as_uint(p[0]);
                af[mt][1] = __float_as_uint(p[8 * SROW]);
                af[mt][2] = __float_as_uint(p[4]);
                af[mt][3] = __float_as_uint(p[8 * SROW + 4]);
            }
#pragma unroll
            for (int nt = 0; nt < 6; nt++) {
                const float* p = bS + nt * 8 * SROW + kk * 8;
                bf[nt][0] = __float_as_uint(p[0]);
                bf[nt][1] = __float_as_uint(p[4]);
            }
#pragma unroll
            for (int mt = 0; mt < 4; mt++)
#pragma unroll
                for (int nt = 0; nt < 6; nt++)
                    mma8(acc[mt][nt], af[mt], bf[nt]);
        }
        if (++st == STAGES) st = 0;
        if (++lst == STAGES) lst = 0;
    }
}

// =============== GEMM1: h = gelu(gather(xr) @ wfc^T + b_fc) ===============
__global__ __launch_bounds__(THREADS, 1)
void fc_kernel(const float* __restrict__ b_fc) {
    int e = blockIdx.y;
    int cnt = g_cnt[e];
    int m0 = blockIdx.x * BM;
    if (m0 >= cnt) return;
    int n0 = blockIdx.z * BN;
    int base = g_base[e];

    extern __shared__ float smf[];
    __shared__ int stok[BM];
    uint32_t sb = smem_u32(smf);
    int tid = threadIdx.x;

    if (tid < BM) {
        int r = m0 + tid;
        stok[tid] = g_tok[e * N_TOK + (r < cnt ? r : 0)];
    }
    __syncthreads();

    const float* aRow = g_xr + (size_t)stok[tid >> 1] * C_DIM + (tid & 1) * 16;
    const float* bRow = g_wfc + (size_t)e * H_DIM * C_DIM + (size_t)(n0 + (tid >> 1)) * C_DIM
                              + (tid & 1) * 16;

    float acc[4][6][4];
#pragma unroll
    for (int i = 0; i < 4; i++)
#pragma unroll
        for (int j = 0; j < 6; j++)
#pragma unroll
            for (int q = 0; q < 4; q++) acc[i][j][q] = 0.0f;

    gemm_mainloop(smf, sb, aRow, bRow, KT1, acc);

    int wid = tid >> 5, lane = tid & 31;
    int wm = wid >> 2, wn = wid & 3;
    int lq = lane >> 2, lr2 = 2 * (lane & 3);
    const float* bp = b_fc + (size_t)e * H_DIM + n0 + wn * 48;
    float bj[6][2];
#pragma unroll
    for (int nt = 0; nt < 6; nt++) {
        bj[nt][0] = bp[nt * 8 + lr2];
        bj[nt][1] = bp[nt * 8 + lr2 + 1];
    }
#pragma unroll
    for (int mt = 0; mt < 4; mt++) {
#pragma unroll
        for (int half = 0; half < 2; half++) {
            int r = m0 + wm * 64 + mt * 16 + lq + half * 8;
            if (r < cnt) {
                float* hp = g_h + (size_t)(base + r) * H_DIM + n0 + wn * 48;
#pragma unroll
                for (int nt = 0; nt < 6; nt++) {
                    float v0 = tf32r(gelu_tanh(acc[mt][nt][2 * half]     + bj[nt][0]));
                    float v1 = tf32r(gelu_tanh(acc[mt][nt][2 * half + 1] + bj[nt][1]));
                    *(float2*)(hp + nt * 8 + lr2) = make_float2(v0, v1);
                }
            }
        }
    }
}

// =============== GEMM2: y = gate * (h @ wp^T + b_proj) ===============
__global__ __launch_bounds__(THREADS, 1)
void proj_kernel(const float* __restrict__ b_proj) {
    int e = blockIdx.y;
    int cnt = g_cnt[e];
    int m0 = blockIdx.x * BM;
    if (m0 >= cnt) return;
    int n0 = blockIdx.z * BN;
    int base = g_base[e];

    extern __shared__ float smf[];
    uint32_t sb = smem_u32(smf);
    int tid = threadIdx.x;

    int rr = m0 + (tid >> 1);
    if (rr >= cnt) rr = cnt - 1;
    const float* aRow = g_h + (size_t)(base + rr) * H_DIM + (tid & 1) * 16;
    const float* bRow = g_wp + (size_t)e * C_DIM * H_DIM + (size_t)(n0 + (tid >> 1)) * H_DIM
                             + (tid & 1) * 16;

    float acc[4][6][4];
#pragma unroll
    for (int i = 0; i < 4; i++)
#pragma unroll
        for (int j = 0; j < 6; j++)
#pragma unroll
            for (int q = 0; q < 4; q++) acc[i][j][q] = 0.0f;

    gemm_mainloop(smf, sb, aRow, bRow, KT2, acc);

    int wid = tid >> 5, lane = tid & 31;
    int wm = wid >> 2, wn = wid & 3;
    int lq = lane >> 2, lr2 = 2 * (lane & 3);
    const float* bp = b_proj + (size_t)e * C_DIM + n0 + wn * 48;
    float bj[6][2];
#pragma unroll
    for (int nt = 0; nt < 6; nt++) {
        bj[nt][0] = bp[nt * 8 + lr2];
        bj[nt][1] = bp[nt * 8 + lr2 + 1];
    }
#pragma unroll
    for (int mt = 0; mt < 4; mt++) {
#pragma unroll
        for (int half = 0; half < 2; half++) {
            int r = m0 + wm * 64 + mt * 16 + lq + half * 8;
            if (r < cnt) {
                float g = g_gate[e * N_TOK + r];
                float* yp = g_y + (size_t)(base + r) * C_DIM + n0 + wn * 48;
#pragma unroll
                for (int nt = 0; nt < 6; nt++) {
                    float v0 = g * (acc[mt][nt][2 * half]     + bj[nt][0]);
                    float v1 = g * (acc[mt][nt][2 * half + 1] + bj[nt][1]);
                    *(float2*)(yp + nt * 8 + lr2) = make_float2(v0, v1);
                }
            }
        }
    }
}

// =============== final gather ===============
__global__ void gather_kernel(float* __restrict__ out) {
    int i = blockIdx.x * blockDim.x + threadIdx.x;
    const int row4 = C_DIM / 4;
    if (i >= N_TOK * row4) return;
    int tok = i / row4;
    int c4 = i - tok * row4;
    int ep0 = g_epos[2 * tok], ep1 = g_epos[2 * tok + 1];
    size_t s0 = (size_t)(g_base[ep0 >> 16] + (ep0 & 0xffff)) * C_DIM + c4 * 4;
    size_t s1 = (size_t)(g_base[ep1 >> 16] + (ep1 & 0xffff)) * C_DIM + c4 * 4;
    float4 a = *(const float4*)(g_y + s0);
    float4 b = *(const float4*)(g_y + s1);
    ((float4*)out)[i] = make_float4(a.x + b.x, a.y + b.y, a.z + b.z, a.w + b.w);
}

// =============== launch ===============
extern "C" void kernel_launch(void* const* d_in, const int* in_sizes, int n_in,
                              void* d_out, int out_size) {
    const float* x      = (const float*)d_in[0];
    const float* gate_w = (const float*)d_in[1];
    const float* gate_b = (const float*)d_in[2];
    const float* w_fc   = (const float*)d_in[3];
    const float* b_fc   = (const float*)d_in[4];
    const float* w_proj = (const float*)d_in[5];
    const float* b_proj = (const float*)d_in[6];
    float* out = (float*)d_out;

    cudaFuncSetAttribute(fc_kernel, cudaFuncAttributeMaxDynamicSharedMemorySize, SMEM_TOTAL);
    cudaFuncSetAttribute(proj_kernel, cudaFuncAttributeMaxDynamicSharedMemorySize, SMEM_TOTAL);

    float* xr_p;  cudaGetSymbolAddress((void**)&xr_p, g_xr);
    float* wfc_p; cudaGetSymbolAddress((void**)&wfc_p, g_wfc);
    float* wp_p;  cudaGetSymbolAddress((void**)&wp_p, g_wp);

    int n4x = N_TOK * C_DIM / 4;
    int n4w = N_EXP * H_DIM * C_DIM / 4;
    round_kernel<<<(n4x + 255) / 256, 256>>>((const float4*)x, (float4*)xr_p, n4x);
    round_kernel<<<(n4w + 255) / 256, 256>>>((const float4*)w_fc, (float4*)wfc_p, n4w);
    round_kernel<<<(n4w + 255) / 256, 256>>>((const float4*)w_proj, (float4*)wp_p, n4w);

    zero_kernel<<<1, 32>>>();
    gate_kernel<<<N_TOK / 8, 256>>>(x, gate_w, gate_b);
    prefix_kernel<<<1, 32>>>();

    fc_kernel<<<dim3(MTILES, N_EXP, H_DIM / BN), THREADS, SMEM_TOTAL>>>(b_fc);
    proj_kernel<<<dim3(MTILES, N_EXP, C_DIM / BN), THREADS, SMEM_TOTAL>>>(b_proj);
    gather_kernel<<<(N_TOK * (C_DIM / 4)) / 256, 256>>>(out);
}

// round 16
// speedup vs baseline: 1.8960x; 1.8960x over previous
#include <cuda_runtime.h>
#include <cuda_fp16.h>
#include <cstdint>
#include <math.h>

#define N_TOK 8192
#define C_DIM 768
#define H_DIM 3072
#define N_EXP 8

#define BM 128
#define BN 256
#define BKH 64                    // K halves per chunk (128 bytes per row)
#define STAGES 3
#define SROW_H 72                 // padded smem row stride (halves) = 144 B
#define A_STAGE_H (BM * SROW_H)   // 9216 halves
#define B_STAGE_H (BN * SROW_H)   // 18432 halves
#define STAGE_H   (A_STAGE_H + B_STAGE_H)     // 27648 halves
#define SMEM_TOTAL (STAGES * STAGE_H * 2)     // 165888 bytes
#define THREADS 512

#define KT1 (C_DIM / BKH)         // 12
#define KT2 (H_DIM / BKH)         // 48

// ---- static device scratch ----
__device__ int    g_cnt[N_EXP];
__device__ int    g_base[N_EXP];
__device__ int    g_tok[N_EXP * N_TOK];
__device__ float  g_gate[N_EXP * N_TOK];
__device__ int    g_epos[2 * N_TOK];
__device__ __half g_h[(size_t)2 * N_TOK * H_DIM];          // fp16 hidden
__device__ float  g_y[(size_t)2 * N_TOK * C_DIM];
__device__ __half g_xh[(size_t)N_TOK * C_DIM];             // fp16 x
__device__ __half g_wfch[(size_t)N_EXP * H_DIM * C_DIM];   // fp16 w_fc
__device__ __half g_wph[(size_t)N_EXP * C_DIM * H_DIM];    // fp16 w_proj

// =============== helpers ===============
__device__ __forceinline__ uint32_t smem_u32(const void* p) {
    uint32_t a;
    asm("{ .reg .u64 t; cvta.to.shared.u64 t, %1; cvt.u32.u64 %0, t; }" : "=r"(a) : "l"(p));
    return a;
}
__device__ __forceinline__ void cp16(uint32_t dst, const void* src) {
    asm volatile("cp.async.cg.shared.global [%0], [%1], 16;" :: "r"(dst), "l"(src) : "memory");
}
__device__ __forceinline__ void cp_commit() { asm volatile("cp.async.commit_group;" ::: "memory"); }
template <int N> __device__ __forceinline__ void cp_wait() {
    asm volatile("cp.async.wait_group %0;" :: "n"(N) : "memory");
}
__device__ __forceinline__ void mma16(float* c, const uint32_t* a, const uint32_t* b) {
    asm volatile(
        "mma.sync.aligned.m16n8k16.row.col.f32.f16.f16.f32 "
        "{%0,%1,%2,%3},{%4,%5,%6,%7},{%8,%9},{%0,%1,%2,%3};"
        : "+f"(c[0]), "+f"(c[1]), "+f"(c[2]), "+f"(c[3])
        : "r"(a[0]), "r"(a[1]), "r"(a[2]), "r"(a[3]), "r"(b[0]), "r"(b[1]));
}
__device__ __forceinline__ float gelu_tanh(float v) {
    float t = 0.7978845608028654f * (v + 0.044715f * v * v * v);
    return 0.5f * v * (1.0f + tanhf(t));
}

// =============== small kernels ===============
__global__ void zero_kernel() {
    if (threadIdx.x < N_EXP) g_cnt[threadIdx.x] = 0;
}

// fp32 -> fp16 conversion (4 elems/thread)
__global__ void cvt_kernel(const float4* __restrict__ src, __half2* __restrict__ dst, int n4) {
    int i = blockIdx.x * blockDim.x + threadIdx.x;
    if (i < n4) {
        float4 v = src[i];
        dst[2 * i]     = __floats2half2_rn(v.x, v.y);
        dst[2 * i + 1] = __floats2half2_rn(v.z, v.w);
    }
}

__global__ void gate_kernel(const float* __restrict__ x,
                            const float* __restrict__ gw,
                            const float* __restrict__ gb) {
    __shared__ float sw[N_EXP * C_DIM];
    for (int i = threadIdx.x; i < N_EXP * C_DIM; i += blockDim.x) sw[i] = gw[i];
    __syncthreads();

    int warp = threadIdx.x >> 5, lane = threadIdx.x & 31;
    int tok = blockIdx.x * 8 + warp;
    const float* xr = x + (size_t)tok * C_DIM;

    float acc[8] = {0, 0, 0, 0, 0, 0, 0, 0};
    for (int c = lane; c < C_DIM; c += 32) {
        float xv = xr[c];
#pragma unroll
        for (int e = 0; e < 8; e++) acc[e] += xv * sw[e * C_DIM + c];
    }
#pragma unroll
    for (int off = 16; off; off >>= 1)
#pragma unroll
        for (int e = 0; e < 8; e++)
            acc[e] += __shfl_down_sync(0xffffffffu, acc[e], off);

    if (lane == 0) {
        float s[8];
#pragma unroll
        for (int e = 0; e < 8; e++) s[e] = acc[e] + gb[e];
        float s0 = s[0]; int e0 = 0;
#pragma unroll
        for (int e = 1; e < 8; e++) if (s[e] > s0) { s0 = s[e]; e0 = e; }
        float s1 = -1e30f; int e1 = 0;
#pragma unroll
        for (int e = 0; e < 8; e++) {
            if (e == e0) continue;
            if (s[e] > s1) { s1 = s[e]; e1 = e; }
        }
        float g0 = 1.0f / (1.0f + expf(s1 - s0));
        float g1 = 1.0f - g0;

        int p0 = atomicAdd(&g_cnt[e0], 1);
        g_tok[e0 * N_TOK + p0] = tok;
        g_gate[e0 * N_TOK + p0] = g0;
        int p1 = atomicAdd(&g_cnt[e1], 1);
        g_tok[e1 * N_TOK + p1] = tok;
        g_gate[e1 * N_TOK + p1] = g1;
        g_epos[2 * tok + 0] = (e0 << 16) | p0;
        g_epos[2 * tok + 1] = (e1 << 16) | p1;
    }
}

__global__ void prefix_kernel() {
    if (threadIdx.x == 0) {
        int b = 0;
        for (int e = 0; e < N_EXP; e++) { g_base[e] = b; b += g_cnt[e]; }
    }
}

// =============== shared fp16 mma.sync mainloop ===============
// CTA tile 128x256, 16 warps in 4x4 grid, warp tile 32x64. 512 threads.
// Chunk = 64 k-halves = 128 B/row.
// A loader: 4 thr/row, 2x cp16 each. B loader: 2 thr/row, 4x cp16 each.
__device__ __forceinline__ void gemm_mainloop(__half* smh, uint32_t sb,
                                              const __half* aRow, const __half* bRow,
                                              int KT, float acc[2][8][4]) {
    int tid = threadIdx.x;
    int wid = tid >> 5, lane = tid & 31;
    int wm = wid >> 2, wn = wid & 3;      // 4x4 warp grid, 32x64 warp tile
    int lq = lane >> 2, lr = lane & 3;

    uint32_t abase = sb + (uint32_t)((tid >> 2) * SROW_H * 2 + (tid & 3) * 32);
    uint32_t bbase = sb + (uint32_t)(A_STAGE_H * 2 + (tid >> 1) * SROW_H * 2 + (tid & 1) * 64);

#pragma unroll
    for (int c = 0; c < STAGES - 1; ++c) {
        uint32_t so = (uint32_t)(c * STAGE_H * 2);
        const __half* as = aRow + c * BKH;
        const __half* bs = bRow + c * BKH;
#pragma unroll
        for (int q = 0; q < 2; q++) cp16(abase + so + q * 16, as + q * 8);
#pragma unroll
        for (int q = 0; q < 4; q++) cp16(bbase + so + q * 16, bs + q * 8);
        cp_commit();
    }

    const __half* aFrag = smh + (wm * 32 + lq) * SROW_H + 2 * lr;
    const __half* bFrag = smh + A_STAGE_H + (wn * 64 + lq) * SROW_H + 2 * lr;

    int st = 0;                    // compute stage
    int lst = STAGES - 1;          // load stage

#pragma unroll 1
    for (int kt = 0; kt < KT; ++kt) {
        cp_wait<STAGES - 2>();
        __syncthreads();

        int lc = kt + STAGES - 1;
        if (lc < KT) {
            uint32_t so = (uint32_t)(lst * STAGE_H * 2);
            const __half* as = aRow + lc * BKH;
            const __half* bs = bRow + lc * BKH;
#pragma unroll
            for (int q = 0; q < 2; q++) cp16(abase + so + q * 16, as + q * 8);
#pragma unroll
            for (int q = 0; q < 4; q++) cp16(bbase + so + q * 16, bs + q * 8);
        }
        cp_commit();   // always commit (keeps wait_group accounting uniform)

        const __half* aS = aFrag + st * STAGE_H;
        const __half* bS = bFrag + st * STAGE_H;

#pragma unroll
        for (int kk = 0; kk < 4; kk++) {    // 4 x k16 = 64 k-halves
            uint32_t af[2][4], bf[8][2];
#pragma unroll
            for (int mt = 0; mt < 2; mt++) {
                const __half* p = aS + mt * 16 * SROW_H + kk * 16;
                af[mt][0] = *(const uint32_t*)(p);
                af[mt][1] = *(const uint32_t*)(p + 8 * SROW_H);
                af[mt][2] = *(const uint32_t*)(p + 8);
                af[mt][3] = *(const uint32_t*)(p + 8 * SROW_H + 8);
            }
#pragma unroll
            for (int nt = 0; nt < 8; nt++) {
                const __half* p = bS + nt * 8 * SROW_H + kk * 16;
                bf[nt][0] = *(const uint32_t*)(p);
                bf[nt][1] = *(const uint32_t*)(p + 8);
            }
#pragma unroll
            for (int mt = 0; mt < 2; mt++)
#pragma unroll
                for (int nt = 0; nt < 8; nt++)
                    mma16(acc[mt][nt], af[mt], bf[nt]);
        }
        if (++st == STAGES) st = 0;
        if (++lst == STAGES) lst = 0;
    }
}

// =============== GEMM1: h = gelu(gather(xh) @ wfc^T + b_fc) ===============
__global__ __launch_bounds__(THREADS, 1)
void fc_kernel(const float* __restrict__ b_fc) {
    int e = blockIdx.y;
    int cnt = g_cnt[e];
    int m0 = blockIdx.x * BM;
    if (m0 >= cnt) return;
    int n0 = blockIdx.z * BN;
    int base = g_base[e];

    extern __shared__ __half smh[];
    __shared__ int stok[BM];
    uint32_t sb = smem_u32(smh);
    int tid = threadIdx.x;

    if (tid < BM) {
        int r = m0 + tid;
        stok[tid] = g_tok[e * N_TOK + (r < cnt ? r : 0)];
    }
    __syncthreads();

    const __half* aRow = g_xh + (size_t)stok[tid >> 2] * C_DIM + (tid & 3) * 16;
    const __half* bRow = g_wfch + (size_t)e * H_DIM * C_DIM + (size_t)(n0 + (tid >> 1)) * C_DIM
                               + (tid & 1) * 32;

    float acc[2][8][4];
#pragma unroll
    for (int i = 0; i < 2; i++)
#pragma unroll
        for (int j = 0; j < 8; j++)
#pragma unroll
            for (int q = 0; q < 4; q++) acc[i][j][q] = 0.0f;

    gemm_mainloop(smh, sb, aRow, bRow, KT1, acc);

    int wid = tid >> 5, lane = tid & 31;
    int wm = wid >> 2, wn = wid & 3;
    int lq = lane >> 2, lr2 = 2 * (lane & 3);
    const float* bp = b_fc + (size_t)e * H_DIM + n0 + wn * 64;
    float bj[8][2];
#pragma unroll
    for (int nt = 0; nt < 8; nt++) {
        bj[nt][0] = bp[nt * 8 + lr2];
        bj[nt][1] = bp[nt * 8 + lr2 + 1];
    }
#pragma unroll
    for (int mt = 0; mt < 2; mt++) {
#pragma unroll
        for (int half = 0; half < 2; half++) {
            int r = m0 + wm * 32 + mt * 16 + lq + half * 8;
            if (r < cnt) {
                __half* hp = g_h + (size_t)(base + r) * H_DIM + n0 + wn * 64;
#pragma unroll
                for (int nt = 0; nt < 8; nt++) {
                    float v0 = gelu_tanh(acc[mt][nt][2 * half]     + bj[nt][0]);
                    float v1 = gelu_tanh(acc[mt][nt][2 * half + 1] + bj[nt][1]);
                    *(__half2*)(hp + nt * 8 + lr2) = __floats2half2_rn(v0, v1);
                }
            }
        }
    }
}

// =============== GEMM2: y = gate * (h @ wp^T + b_proj) ===============
__global__ __launch_bounds__(THREADS, 1)
void proj_kernel(const float* __restrict__ b_proj) {
    int e = blockIdx.y;
    int cnt = g_cnt[e];
    int m0 = blockIdx.x * BM;
    if (m0 >= cnt) return;
    int n0 = blockIdx.z * BN;
    int base = g_base[e];

    extern __shared__ __half smh[];
    uint32_t sb = smem_u32(smh);
    int tid = threadIdx.x;

    int rr = m0 + (tid >> 2);
    if (rr >= cnt) rr = cnt - 1;
    const __half* aRow = g_h + (size_t)(base + rr) * H_DIM + (tid & 3) * 16;
    const __half* bRow = g_wph + (size_t)e * C_DIM * H_DIM + (size_t)(n0 + (tid >> 1)) * H_DIM
                              + (tid & 1) * 32;

    float acc[2][8][4];
#pragma unroll
    for (int i = 0; i < 2; i++)
#pragma unroll
        for (int j = 0; j < 8; j++)
#pragma unroll
            for (int q = 0; q < 4; q++) acc[i][j][q] = 0.0f;

    gemm_mainloop(smh, sb, aRow, bRow, KT2, acc);

    int wid = tid >> 5, lane = tid & 31;
    int wm = wid >> 2, wn = wid & 3;
    int lq = lane >> 2, lr2 = 2 * (lane & 3);
    const float* bp = b_proj + (size_t)e * C_DIM + n0 + wn * 64;
    float bj[8][2];
#pragma unroll
    for (int nt = 0; nt < 8; nt++) {
        bj[nt][0] = bp[nt * 8 + lr2];
        bj[nt][1] = bp[nt * 8 + lr2 + 1];
    }
#pragma unroll
    for (int mt = 0; mt < 2; mt++) {
#pragma unroll
        for (int half = 0; half < 2; half++) {
            int r = m0 + wm * 32 + mt * 16 + lq + half * 8;
            if (r < cnt) {
                float g = g_gate[e * N_TOK + r];
                float* yp = g_y + (size_t)(base + r) * C_DIM + n0 + wn * 64;
#pragma unroll
                for (int nt = 0; nt < 8; nt++) {
                    float v0 = g * (acc[mt][nt][2 * half]     + bj[nt][0]);
                    float v1 = g * (acc[mt][nt][2 * half + 1] + bj[nt][1]);
                    *(float2*)(yp + nt * 8 + lr2) = make_float2(v0, v1);
                }
            }
        }
    }
}

// =============== final gather ===============
__global__ void gather_kernel(float* __restrict__ out) {
    int i = blockIdx.x * blockDim.x + threadIdx.x;
    const int row4 = C_DIM / 4;
    if (i >= N_TOK * row4) return;
    int tok = i / row4;
    int c4 = i - tok * row4;
    int ep0 = g_epos[2 * tok], ep1 = g_epos[2 * tok + 1];
    size_t s0 = (size_t)(g_base[ep0 >> 16] + (ep0 & 0xffff)) * C_DIM + c4 * 4;
    size_t s1 = (size_t)(g_base[ep1 >> 16] + (ep1 & 0xffff)) * C_DIM + c4 * 4;
    float4 a = *(const float4*)(g_y + s0);
    float4 b = *(const float4*)(g_y + s1);
    ((float4*)out)[i] = make_float4(a.x + b.x, a.y + b.y, a.z + b.z, a.w + b.w);
}

// =============== launch ===============
extern "C" void kernel_launch(void* const* d_in, const int* in_sizes, int n_in,
                              void* d_out, int out_size) {
    const float* x      = (const float*)d_in[0];
    const float* gate_w = (const float*)d_in[1];
    const float* gate_b = (const float*)d_in[2];
    const float* w_fc   = (const float*)d_in[3];
    const float* b_fc   = (const float*)d_in[4];
    const float* w_proj = (const float*)d_in[5];
    const float* b_proj = (const float*)d_in[6];
    float* out = (float*)d_out;

    cudaFuncSetAttribute(fc_kernel, cudaFuncAttributeMaxDynamicSharedMemorySize, SMEM_TOTAL);
    cudaFuncSetAttribute(proj_kernel, cudaFuncAttributeMaxDynamicSharedMemorySize, SMEM_TOTAL);

    __half* xh_p;  cudaGetSymbolAddress((void**)&xh_p, g_xh);
    __half* wfc_p; cudaGetSymbolAddress((void**)&wfc_p, g_wfch);
    __half* wp_p;  cudaGetSymbolAddress((void**)&wp_p, g_wph);

    int n4x = N_TOK * C_DIM / 4;
    int n4w = N_EXP * H_DIM * C_DIM / 4;
    cvt_kernel<<<(n4x + 255) / 256, 256>>>((const float4*)x, (__half2*)xh_p, n4x);
    cvt_kernel<<<(n4w + 255) / 256, 256>>>((const float4*)w_fc, (__half2*)wfc_p, n4w);
    cvt_kernel<<<(n4w + 255) / 256, 256>>>((const float4*)w_proj, (__half2*)wp_p, n4w);

    zero_kernel<<<1, 32>>>();
    gate_kernel<<<N_TOK / 8, 256>>>(x, gate_w, gate_b);
    prefix_kernel<<<1, 32>>>();

    fc_kernel<<<dim3(N_TOK / BM, N_EXP, H_DIM / BN), THREADS, SMEM_TOTAL>>>(b_fc);
    proj_kernel<<<dim3(N_TOK / BM, N_EXP, C_DIM / BN), THREADS, SMEM_TOTAL>>>(b_proj);
    gather_kernel<<<(N_TOK * (C_DIM / 4)) / 256, 256>>>(out);
}

// round 17
// speedup vs baseline: 2.0607x; 1.0869x over previous
#include <cuda_runtime.h>
#include <cuda_fp16.h>
#include <cstdint>
#include <math.h>

#define N_TOK 8192
#define C_DIM 768
#define H_DIM 3072
#define N_EXP 8

#define BM 128
#define BN 256
#define BKH 64                    // K halves per chunk (128 bytes per row)
#define STAGES 3
#define SROW_H 72                 // padded smem row stride (halves) = 144 B
#define A_STAGE_H (BM * SROW_H)   // 9216 halves
#define B_STAGE_H (BN * SROW_H)   // 18432 halves
#define STAGE_H   (A_STAGE_H + B_STAGE_H)     // 27648 halves
#define SMEM_TOTAL (STAGES * STAGE_H * 2)     // 165888 bytes
#define THREADS 512

#define KT1 (C_DIM / BKH)         // 12
#define KT2 (H_DIM / BKH)         // 48

// ---- static device scratch ----
__device__ int    g_cnt[N_EXP];
__device__ int    g_base[N_EXP];
__device__ int    g_tok[N_EXP * N_TOK];
__device__ float  g_gate[N_EXP * N_TOK];
__device__ int    g_epos[2 * N_TOK];
__device__ __half g_h[(size_t)2 * N_TOK * H_DIM];          // fp16 hidden
__device__ float  g_y[(size_t)2 * N_TOK * C_DIM];
__device__ __half g_xh[(size_t)N_TOK * C_DIM];             // fp16 x
__device__ __half g_wfch[(size_t)N_EXP * H_DIM * C_DIM];   // fp16 w_fc
__device__ __half g_wph[(size_t)N_EXP * C_DIM * H_DIM];    // fp16 w_proj

// =============== helpers ===============
__device__ __forceinline__ uint32_t smem_u32(const void* p) {
    uint32_t a;
    asm("{ .reg .u64 t; cvta.to.shared.u64 t, %1; cvt.u32.u64 %0, t; }" : "=r"(a) : "l"(p));
    return a;
}
__device__ __forceinline__ void cp16(uint32_t dst, const void* src) {
    asm volatile("cp.async.cg.shared.global [%0], [%1], 16;" :: "r"(dst), "l"(src) : "memory");
}
__device__ __forceinline__ void cp_commit() { asm volatile("cp.async.commit_group;" ::: "memory"); }
template <int N> __device__ __forceinline__ void cp_wait() {
    asm volatile("cp.async.wait_group %0;" :: "n"(N) : "memory");
}
__device__ __forceinline__ void ldsm4(uint32_t& r0, uint32_t& r1, uint32_t& r2, uint32_t& r3,
                                      uint32_t addr) {
    asm volatile("ldmatrix.sync.aligned.m8n8.x4.shared.b16 {%0,%1,%2,%3}, [%4];"
                 : "=r"(r0), "=r"(r1), "=r"(r2), "=r"(r3) : "r"(addr));
}
__device__ __forceinline__ void mma16(float* c, const uint32_t* a, const uint32_t* b) {
    asm volatile(
        "mma.sync.aligned.m16n8k16.row.col.f32.f16.f16.f32 "
        "{%0,%1,%2,%3},{%4,%5,%6,%7},{%8,%9},{%0,%1,%2,%3};"
        : "+f"(c[0]), "+f"(c[1]), "+f"(c[2]), "+f"(c[3])
        : "r"(a[0]), "r"(a[1]), "r"(a[2]), "r"(a[3]), "r"(b[0]), "r"(b[1]));
}
__device__ __forceinline__ float gelu_tanh(float v) {
    float t = 0.7978845608028654f * (v + 0.044715f * v * v * v);
    return 0.5f * v * (1.0f + tanhf(t));
}

// =============== small kernels ===============
__global__ void zero_kernel() {
    if (threadIdx.x < N_EXP) g_cnt[threadIdx.x] = 0;
}

// fp32 -> fp16 conversion (4 elems/thread)
__global__ void cvt_kernel(const float4* __restrict__ src, __half2* __restrict__ dst, int n4) {
    int i = blockIdx.x * blockDim.x + threadIdx.x;
    if (i < n4) {
        float4 v = src[i];
        dst[2 * i]     = __floats2half2_rn(v.x, v.y);
        dst[2 * i + 1] = __floats2half2_rn(v.z, v.w);
    }
}

__global__ void gate_kernel(const float* __restrict__ x,
                            const float* __restrict__ gw,
                            const float* __restrict__ gb) {
    __shared__ float sw[N_EXP * C_DIM];
    for (int i = threadIdx.x; i < N_EXP * C_DIM; i += blockDim.x) sw[i] = gw[i];
    __syncthreads();

    int warp = threadIdx.x >> 5, lane = threadIdx.x & 31;
    int tok = blockIdx.x * 8 + warp;
    const float* xr = x + (size_t)tok * C_DIM;

    float acc[8] = {0, 0, 0, 0, 0, 0, 0, 0};
    for (int c = lane; c < C_DIM; c += 32) {
        float xv = xr[c];
#pragma unroll
        for (int e = 0; e < 8; e++) acc[e] += xv * sw[e * C_DIM + c];
    }
#pragma unroll
    for (int off = 16; off; off >>= 1)
#pragma unroll
        for (int e = 0; e < 8; e++)
            acc[e] += __shfl_down_sync(0xffffffffu, acc[e], off);

    if (lane == 0) {
        float s[8];
#pragma unroll
        for (int e = 0; e < 8; e++) s[e] = acc[e] + gb[e];
        float s0 = s[0]; int e0 = 0;
#pragma unroll
        for (int e = 1; e < 8; e++) if (s[e] > s0) { s0 = s[e]; e0 = e; }
        float s1 = -1e30f; int e1 = 0;
#pragma unroll
        for (int e = 0; e < 8; e++) {
            if (e == e0) continue;
            if (s[e] > s1) { s1 = s[e]; e1 = e; }
        }
        float g0 = 1.0f / (1.0f + expf(s1 - s0));
        float g1 = 1.0f - g0;

        int p0 = atomicAdd(&g_cnt[e0], 1);
        g_tok[e0 * N_TOK + p0] = tok;
        g_gate[e0 * N_TOK + p0] = g0;
        int p1 = atomicAdd(&g_cnt[e1], 1);
        g_tok[e1 * N_TOK + p1] = tok;
        g_gate[e1 * N_TOK + p1] = g1;
        g_epos[2 * tok + 0] = (e0 << 16) | p0;
        g_epos[2 * tok + 1] = (e1 << 16) | p1;
    }
}

__global__ void prefix_kernel() {
    if (threadIdx.x == 0) {
        int b = 0;
        for (int e = 0; e < N_EXP; e++) { g_base[e] = b; b += g_cnt[e]; }
    }
}

// =============== shared fp16 mma.sync mainloop (ldmatrix frags) ===============
// CTA tile 128x256, 16 warps in 4x4 grid, warp tile 32x64. 512 threads.
__device__ __forceinline__ void gemm_mainloop(__half* smh, uint32_t sb,
                                              const __half* aRow, const __half* bRow,
                                              int KT, float acc[2][8][4]) {
    int tid = threadIdx.x;
    int wid = tid >> 5, lane = tid & 31;
    int wm = wid >> 2, wn = wid & 3;      // 4x4 warp grid, 32x64 warp tile

    uint32_t abase = sb + (uint32_t)((tid >> 2) * SROW_H * 2 + (tid & 3) * 32);
    uint32_t bbase = sb + (uint32_t)(A_STAGE_H * 2 + (tid >> 1) * SROW_H * 2 + (tid & 1) * 64);

    // ldmatrix lane addresses (byte offsets in shared space)
    // A x4: mats (m0-7,k0-7),(m8-15,k0-7),(m0-7,k8-15),(m8-15,k8-15)
    uint32_t aBase = sb + (uint32_t)((((wm * 32) + (lane & 15)) * SROW_H + (lane >> 4) * 8) * 2);
    // B x4: mats (nt,k0-7),(nt,k8-15),(nt+1,k0-7),(nt+1,k8-15)
    uint32_t bBase = sb + (uint32_t)(A_STAGE_H * 2 +
        (((wn * 64) + (lane & 7) + ((lane >> 4) & 1) * 8) * SROW_H + ((lane >> 3) & 1) * 8) * 2);

#pragma unroll
    for (int c = 0; c < STAGES - 1; ++c) {
        uint32_t so = (uint32_t)(c * STAGE_H * 2);
        const __half* as = aRow + c * BKH;
        const __half* bs = bRow + c * BKH;
#pragma unroll
        for (int q = 0; q < 2; q++) cp16(abase + so + q * 16, as + q * 8);
#pragma unroll
        for (int q = 0; q < 4; q++) cp16(bbase + so + q * 16, bs + q * 8);
        cp_commit();
    }

    int st = 0;                    // compute stage
    int lst = STAGES - 1;          // load stage

#pragma unroll 1
    for (int kt = 0; kt < KT; ++kt) {
        cp_wait<STAGES - 2>();
        __syncthreads();

        int lc = kt + STAGES - 1;
        if (lc < KT) {
            uint32_t so = (uint32_t)(lst * STAGE_H * 2);
            const __half* as = aRow + lc * BKH;
            const __half* bs = bRow + lc * BKH;
#pragma unroll
            for (int q = 0; q < 2; q++) cp16(abase + so + q * 16, as + q * 8);
#pragma unroll
            for (int q = 0; q < 4; q++) cp16(bbase + so + q * 16, bs + q * 8);
        }
        cp_commit();   // always commit (keeps wait_group accounting uniform)

        uint32_t aSt = aBase + (uint32_t)(st * STAGE_H * 2);
        uint32_t bSt = bBase + (uint32_t)(st * STAGE_H * 2);

#pragma unroll
        for (int kk = 0; kk < 4; kk++) {    // 4 x k16 = 64 k-halves
            uint32_t af[2][4], bf[8][2];
#pragma unroll
            for (int mt = 0; mt < 2; mt++)
                ldsm4(af[mt][0], af[mt][1], af[mt][2], af[mt][3],
                      aSt + (uint32_t)(mt * 16 * SROW_H * 2 + kk * 32));
#pragma unroll
            for (int j = 0; j < 4; j++)
                ldsm4(bf[2 * j][0], bf[2 * j][1], bf[2 * j + 1][0], bf[2 * j + 1][1],
                      bSt + (uint32_t)(j * 16 * SROW_H * 2 + kk * 32));
#pragma unroll
            for (int mt = 0; mt < 2; mt++)
#pragma unroll
                for (int nt = 0; nt < 8; nt++)
                    mma16(acc[mt][nt], af[mt], bf[nt]);
        }
        if (++st == STAGES) st = 0;
        if (++lst == STAGES) lst = 0;
    }
}

// =============== GEMM1: h = gelu(gather(xh) @ wfc^T + b_fc) ===============
__global__ __launch_bounds__(THREADS, 1)
void fc_kernel(const float* __restrict__ b_fc) {
    int e = blockIdx.y;
    int cnt = g_cnt[e];
    int m0 = blockIdx.x * BM;
    if (m0 >= cnt) return;
    int n0 = blockIdx.z * BN;
    int base = g_base[e];

    extern __shared__ __half smh[];
    __shared__ int stok[BM];
    uint32_t sb = smem_u32(smh);
    int tid = threadIdx.x;

    if (tid < BM) {
        int r = m0 + tid;
        stok[tid] = g_tok[e * N_TOK + (r < cnt ? r : 0)];
    }
    __syncthreads();

    const __half* aRow = g_xh + (size_t)stok[tid >> 2] * C_DIM + (tid & 3) * 16;
    const __half* bRow = g_wfch + (size_t)e * H_DIM * C_DIM + (size_t)(n0 + (tid >> 1)) * C_DIM
                               + (tid & 1) * 32;

    float acc[2][8][4];
#pragma unroll
    for (int i = 0; i < 2; i++)
#pragma unroll
        for (int j = 0; j < 8; j++)
#pragma unroll
            for (int q = 0; q < 4; q++) acc[i][j][q] = 0.0f;

    gemm_mainloop(smh, sb, aRow, bRow, KT1, acc);

    int wid = tid >> 5, lane = tid & 31;
    int wm = wid >> 2, wn = wid & 3;
    int lq = lane >> 2, lr2 = 2 * (lane & 3);
    const float* bp = b_fc + (size_t)e * H_DIM + n0 + wn * 64;
    float bj[8][2];
#pragma unroll
    for (int nt = 0; nt < 8; nt++) {
        bj[nt][0] = bp[nt * 8 + lr2];
        bj[nt][1] = bp[nt * 8 + lr2 + 1];
    }
#pragma unroll
    for (int mt = 0; mt < 2; mt++) {
#pragma unroll
        for (int half = 0; half < 2; half++) {
            int r = m0 + wm * 32 + mt * 16 + lq + half * 8;
            if (r < cnt) {
                __half* hp = g_h + (size_t)(base + r) * H_DIM + n0 + wn * 64;
#pragma unroll
                for (int nt = 0; nt < 8; nt++) {
                    float v0 = gelu_tanh(acc[mt][nt][2 * half]     + bj[nt][0]);
                    float v1 = gelu_tanh(acc[mt][nt][2 * half + 1] + bj[nt][1]);
                    *(__half2*)(hp + nt * 8 + lr2) = __floats2half2_rn(v0, v1);
                }
            }
        }
    }
}

// =============== GEMM2: y = gate * (h @ wp^T + b_proj) ===============
__global__ __launch_bounds__(THREADS, 1)
void proj_kernel(const float* __restrict__ b_proj) {
    int e = blockIdx.y;
    int cnt = g_cnt[e];
    int m0 = blockIdx.x * BM;
    if (m0 >= cnt) return;
    int n0 = blockIdx.z * BN;
    int base = g_base[e];

    extern __shared__ __half smh[];
    uint32_t sb = smem_u32(smh);
    int tid = threadIdx.x;

    int rr = m0 + (tid >> 2);
    if (rr >= cnt) rr = cnt - 1;
    const __half* aRow = g_h + (size_t)(base + rr) * H_DIM + (tid & 3) * 16;
    const __half* bRow = g_wph + (size_t)e * C_DIM * H_DIM + (size_t)(n0 + (tid >> 1)) * H_DIM
                              + (tid & 1) * 32;

    float acc[2][8][4];
#pragma unroll
    for (int i = 0; i < 2; i++)
#pragma unroll
        for (int j = 0; j < 8; j++)
#pragma unroll
            for (int q = 0; q < 4; q++) acc[i][j][q] = 0.0f;

    gemm_mainloop(smh, sb, aRow, bRow, KT2, acc);

    int wid = tid >> 5, lane = tid & 31;
    int wm = wid >> 2, wn = wid & 3;
    int lq = lane >> 2, lr2 = 2 * (lane & 3);
    const float* bp = b_proj + (size_t)e * C_DIM + n0 + wn * 64;
    float bj[8][2];
#pragma unroll
    for (int nt = 0; nt < 8; nt++) {
        bj[nt][0] = bp[nt * 8 + lr2];
        bj[nt][1] = bp[nt * 8 + lr2 + 1];
    }
#pragma unroll
    for (int mt = 0; mt < 2; mt++) {
#pragma unroll
        for (int half = 0; half < 2; half++) {
            int r = m0 + wm * 32 + mt * 16 + lq + half * 8;
            if (r < cnt) {
                float g = g_gate[e * N_TOK + r];
                float* yp = g_y + (size_t)(base + r) * C_DIM + n0 + wn * 64;
#pragma unroll
                for (int nt = 0; nt < 8; nt++) {
                    float v0 = g * (acc[mt][nt][2 * half]     + bj[nt][0]);
                    float v1 = g * (acc[mt][nt][2 * half + 1] + bj[nt][1]);
                    *(float2*)(yp + nt * 8 + lr2) = make_float2(v0, v1);
                }
            }
        }
    }
}

// =============== final gather ===============
__global__ void gather_kernel(float* __restrict__ out) {
    int i = blockIdx.x * blockDim.x + threadIdx.x;
    const int row4 = C_DIM / 4;
    if (i >= N_TOK * row4) return;
    int tok = i / row4;
    int c4 = i - tok * row4;
    int ep0 = g_epos[2 * tok], ep1 = g_epos[2 * tok + 1];
    size_t s0 = (size_t)(g_base[ep0 >> 16] + (ep0 & 0xffff)) * C_DIM + c4 * 4;
    size_t s1 = (size_t)(g_base[ep1 >> 16] + (ep1 & 0xffff)) * C_DIM + c4 * 4;
    float4 a = *(const float4*)(g_y + s0);
    float4 b = *(const float4*)(g_y + s1);
    ((float4*)out)[i] = make_float4(a.x + b.x, a.y + b.y, a.z + b.z, a.w + b.w);
}

// =============== launch ===============
extern "C" void kernel_launch(void* const* d_in, const int* in_sizes, int n_in,
                              void* d_out, int out_size) {
    const float* x      = (const float*)d_in[0];
    const float* gate_w = (const float*)d_in[1];
    const float* gate_b = (const float*)d_in[2];
    const float* w_fc   = (const float*)d_in[3];
    const float* b_fc   = (const float*)d_in[4];
    const float* w_proj = (const float*)d_in[5];
    const float* b_proj = (const float*)d_in[6];
    float* out = (float*)d_out;

    cudaFuncSetAttribute(fc_kernel, cudaFuncAttributeMaxDynamicSharedMemorySize, SMEM_TOTAL);
    cudaFuncSetAttribute(proj_kernel, cudaFuncAttributeMaxDynamicSharedMemorySize, SMEM_TOTAL);

    __half* xh_p;  cudaGetSymbolAddress((void**)&xh_p, g_xh);
    __half* wfc_p; cudaGetSymbolAddress((void**)&wfc_p, g_wfch);
    __half* wp_p;  cudaGetSymbolAddress((void**)&wp_p, g_wph);

    int n4x = N_TOK * C_DIM / 4;
    int n4w = N_EXP * H_DIM * C_DIM / 4;
    cvt_kernel<<<(n4x + 255) / 256, 256>>>((const float4*)x, (__half2*)xh_p, n4x);
    cvt_kernel<<<(n4w + 255) / 256, 256>>>((const float4*)w_fc, (__half2*)wfc_p, n4w);
    cvt_kernel<<<(n4w + 255) / 256, 256>>>((const float4*)w_proj, (__half2*)wp_p, n4w);

    zero_kernel<<<1, 32>>>();
    gate_kernel<<<N_TOK / 8, 256>>>(x, gate_w, gate_b);
    prefix_kernel<<<1, 32>>>();

    fc_kernel<<<dim3(N_TOK / BM, N_EXP, H_DIM / BN), THREADS, SMEM_TOTAL>>>(b_fc);
    proj_kernel<<<dim3(N_TOK / BM, N_EXP, C_DIM / BN), THREADS, SMEM_TOTAL>>>(b_proj);
    gather_kernel<<<(N_TOK * (C_DIM / 4)) / 256, 256>>>(out);
}